// round 1
// baseline (speedup 1.0000x reference)
#include <cuda_runtime.h>
#include <cstdint>

#define B_   16
#define C_   256
#define NHh  8
#define Dh   32
#define Np   4096
#define Kl   64
#define C4_  1024

// ---------------- scratch (static __device__; no allocation) ----------------
__device__ float g_xs  [(size_t)B_*Np*C_];    // (B,N,C) input transposed
__device__ float g_h   [(size_t)B_*Np*C_];    // LN output
__device__ float g_qkvv[(size_t)B_*Np*C4_];   // GEMM1 output (B,N,1024)
__device__ float g_sumsq[B_*512];             // col sum-of-squares (q cols 0..255, k cols 256..511)
__device__ float g_kproj[B_*C_*Kl];           // (b, h*32+dd, kk)
__device__ float g_vproj[B_*C_*Kl];
__device__ float g_attnca[B_*NHh*Dh*Dh];      // softmaxed channel attn
__device__ float g_xsa [(size_t)B_*Np*C_];    // spatial attn out (scrambled flat layout)
__device__ float g_skip[(size_t)B_*C_*Np];    // attn_skip (B,C,N)
__device__ float g_y1  [(size_t)B_*C_*Np];    // conv1 raw
__device__ float g_y3  [(size_t)B_*C_*Np];    // conv2 raw
__device__ float g_s1[C_], g_sh1[C_], g_s2[C_], g_sh2[C_];  // bn scale/shift

// ---------------- 1. transpose + LayerNorm ----------------
__global__ void k_tln(const float* __restrict__ x, const float* __restrict__ lw,
                      const float* __restrict__ lb)
{
    __shared__ float sm[32][C_+1];
    int b = blockIdx.y, n0 = blockIdx.x*32;
    int tx = threadIdx.x & 31, ty = threadIdx.x >> 5;     // 8 warps
    const float* xb = x + (size_t)b*C_*Np + n0 + tx;
    #pragma unroll
    for (int c = ty; c < C_; c += 8)
        sm[tx][c] = xb[(size_t)c*Np];
    __syncthreads();
    #pragma unroll
    for (int rr = 0; rr < 4; ++rr){
        int r = ty*4 + rr;
        float s1 = 0.f, s2 = 0.f;
        #pragma unroll
        for (int c = tx; c < C_; c += 32){ float v = sm[r][c]; s1 += v; s2 += v*v; }
        #pragma unroll
        for (int o = 16; o; o >>= 1){
            s1 += __shfl_xor_sync(0xffffffffu, s1, o);
            s2 += __shfl_xor_sync(0xffffffffu, s2, o);
        }
        float mean = s1 * (1.f/C_);
        float var  = s2 * (1.f/C_) - mean*mean;
        float rstd = rsqrtf(var + 1e-5f);
        size_t row = ((size_t)b*Np + n0 + r)*C_;
        #pragma unroll
        for (int c = tx; c < C_; c += 32){
            float v = sm[r][c];
            g_xs[row+c] = v;
            g_h [row+c] = (v-mean)*rstd*lw[c] + lb[c];
        }
    }
}

// ---------------- 2. qkvv GEMM: (65536 x 256) @ (1024 x 256)^T ----------------
__global__ void __launch_bounds__(256) k_gemm_qkvv(const float* __restrict__ Wq)
{
    __shared__ float As[8][128];
    __shared__ float Bs[8][128];
    int t  = threadIdx.x;
    int n0 = blockIdx.x*128, m0 = blockIdx.y*128;
    int lr = t>>1, lk = (t&1)*4;
    int tm = t>>4, tn = t&15;
    float acc[8][8];
    #pragma unroll
    for (int i=0;i<8;i++)
        #pragma unroll
        for (int j=0;j<8;j++) acc[i][j]=0.f;
    const float* Arow = g_h + (size_t)(m0+lr)*C_ + lk;
    const float* Brow = Wq  + (size_t)(n0+lr)*C_ + lk;
    for (int k0=0;k0<C_;k0+=8){
        float4 av = *(const float4*)(Arow + k0);
        float4 bv = *(const float4*)(Brow + k0);
        As[lk+0][lr]=av.x; As[lk+1][lr]=av.y; As[lk+2][lr]=av.z; As[lk+3][lr]=av.w;
        Bs[lk+0][lr]=bv.x; Bs[lk+1][lr]=bv.y; Bs[lk+2][lr]=bv.z; Bs[lk+3][lr]=bv.w;
        __syncthreads();
        #pragma unroll
        for (int kk=0;kk<8;kk++){
            float4 a0=*(const float4*)&As[kk][tm*8];
            float4 a1=*(const float4*)&As[kk][tm*8+4];
            float4 b0=*(const float4*)&Bs[kk][tn*8];
            float4 b1=*(const float4*)&Bs[kk][tn*8+4];
            float aa[8]={a0.x,a0.y,a0.z,a0.w,a1.x,a1.y,a1.z,a1.w};
            float bb[8]={b0.x,b0.y,b0.z,b0.w,b1.x,b1.y,b1.z,b1.w};
            #pragma unroll
            for (int i=0;i<8;i++)
                #pragma unroll
                for (int j=0;j<8;j++) acc[i][j] += aa[i]*bb[j];
        }
        __syncthreads();
    }
    #pragma unroll
    for (int i=0;i<8;i++){
        float* dst = g_qkvv + (size_t)(m0+tm*8+i)*C4_ + n0 + tn*8;
        *(float4*)(dst)   = make_float4(acc[i][0],acc[i][1],acc[i][2],acc[i][3]);
        *(float4*)(dst+4) = make_float4(acc[i][4],acc[i][5],acc[i][6],acc[i][7]);
    }
}

// ---------------- 3. q/k column sum-of-squares (for l2norm over N) ----------------
__global__ void k_zerosumsq(){
    int i = blockIdx.x*1024 + threadIdx.x;
    if (i < B_*512) g_sumsq[i] = 0.f;
}
__global__ void k_colsumsq(){
    int b = blockIdx.y, chunk = blockIdx.x;
    int c = threadIdx.x;                         // 0..511  (q + k columns)
    size_t base = (size_t)b*Np*C4_ + (size_t)chunk*256*C4_;
    float s = 0.f;
    for (int n=0;n<256;n++){ float v = g_qkvv[base + (size_t)n*C4_ + c]; s += v*v; }
    atomicAdd(&g_sumsq[b*512 + c], s);
}

// ---------------- 4. k_proj / v_proj: per-b (256 x 4096) @ (4096 x 64) ----------------
__global__ void __launch_bounds__(256) k_kvproj(const float* __restrict__ ef)
{
    int b = blockIdx.z, which = blockIdx.y, c0 = blockIdx.x*64;
    int basecol = which ? 768 : 256;             // v_sa cols : k cols
    float* outp = which ? g_vproj : g_kproj;
    __shared__ float a_s[32][65];
    __shared__ float e_s[32][65];
    int t = threadIdx.x, tm = t>>4, tn = t&15;
    float acc[4][4];
    #pragma unroll
    for (int i=0;i<4;i++)
        #pragma unroll
        for (int j=0;j<4;j++) acc[i][j]=0.f;
    for (int n0=0;n0<Np;n0+=32){
        for (int i=t;i<32*64;i+=256){
            int nn=i>>6, cc=i&63;
            a_s[nn][cc] = g_qkvv[((size_t)b*Np + n0+nn)*C4_ + basecol + c0 + cc];
        }
        for (int i=t;i<32*64;i+=256){
            int nn=i>>6, cc=i&63;
            e_s[nn][cc] = ef[(size_t)(n0+nn)*Kl + cc];
        }
        __syncthreads();
        #pragma unroll 8
        for (int nn=0;nn<32;nn++){
            float ra[4], rb[4];
            #pragma unroll
            for (int i=0;i<4;i++) ra[i]=a_s[nn][tm*4+i];
            #pragma unroll
            for (int j=0;j<4;j++) rb[j]=e_s[nn][tn*4+j];
            #pragma unroll
            for (int i=0;i<4;i++)
                #pragma unroll
                for (int j=0;j<4;j++) acc[i][j] += ra[i]*rb[j];
        }
        __syncthreads();
    }
    #pragma unroll
    for (int i=0;i<4;i++)
        #pragma unroll
        for (int j=0;j<4;j++)
            outp[(size_t)b*C_*Kl + (size_t)(c0+tm*4+i)*Kl + tn*4+j] = acc[i][j];
}

// ---------------- 5. channel-attn gram + scale + softmax ----------------
__global__ void __launch_bounds__(1024) k_gram()
{
    int h = blockIdx.x, b = blockIdx.y;
    int t = threadIdx.x, dd = t>>5, e = t&31;
    __shared__ float sm[64][65];                 // 64 n x (32 q | 32 k)
    float s = 0.f;
    for (int n0=0;n0<Np;n0+=64){
        for (int i=t;i<64*64;i+=1024){
            int nn=i>>6, cc=i&63;
            int col = (cc<32) ? (h*32+cc) : (256 + h*32 + (cc-32));
            sm[nn][cc] = g_qkvv[((size_t)b*Np + n0+nn)*C4_ + col];
        }
        __syncthreads();
        #pragma unroll 16
        for (int nn=0;nn<64;nn++) s += sm[nn][dd]*sm[nn][32+e];
        __syncthreads();
    }
    float nq = sqrtf(g_sumsq[b*512 +       h*32 + dd]);
    float nk = sqrtf(g_sumsq[b*512 + 256 + h*32 + e ]);
    float logit = s / fmaxf(nq,1e-12f) / fmaxf(nk,1e-12f) * (1.0f/64.0f);  // /sqrt(N)
    float mx = logit;
    #pragma unroll
    for (int o=16;o;o>>=1) mx = fmaxf(mx, __shfl_xor_sync(0xffffffffu, mx, o));
    float ew = __expf(logit - mx);
    float sw = ew;
    #pragma unroll
    for (int o=16;o;o>>=1) sw += __shfl_xor_sync(0xffffffffu, sw, o);
    g_attnca[((size_t)(b*NHh+h)*Dh + dd)*Dh + e] = ew/sw;
}

// ---------------- 6. spatial (Linformer) attention, online softmax ----------------
__global__ void __launch_bounds__(128) k_spatial(const float* __restrict__ t2)
{
    int b = blockIdx.z, h = blockIdx.y;
    int n = blockIdx.x*128 + threadIdx.x;
    __shared__ float kp[32][65];
    __shared__ float vp[32][65];
    __shared__ float iq_s[32];
    int t = threadIdx.x;
    for (int i=t;i<32*64;i+=128){
        int ddi=i>>6, kki=i&63;
        size_t o = (size_t)b*C_*Kl + (size_t)(h*32+ddi)*Kl + kki;
        kp[ddi][kki]=g_kproj[o];
        vp[ddi][kki]=g_vproj[o];
    }
    if (t<32) iq_s[t] = 1.f/fmaxf(sqrtf(g_sumsq[b*512 + h*32 + t]), 1e-12f);
    __syncthreads();
    float q[32];
    size_t qb = ((size_t)b*Np + n)*C4_ + h*32;
    const float4* qv = (const float4*)(g_qkvv + qb);
    #pragma unroll
    for (int i=0;i<8;i++){
        float4 v = qv[i];
        q[4*i+0]=v.x*iq_s[4*i+0]; q[4*i+1]=v.y*iq_s[4*i+1];
        q[4*i+2]=v.z*iq_s[4*i+2]; q[4*i+3]=v.w*iq_s[4*i+3];
    }
    float temp = t2[h];
    float m = -1e30f, sw = 0.f, acc[32];
    #pragma unroll
    for (int d2=0;d2<32;d2++) acc[d2]=0.f;
    for (int kkx=0;kkx<64;kkx++){
        float s = 0.f;
        #pragma unroll
        for (int d2=0;d2<32;d2++) s += q[d2]*kp[d2][kkx];
        s *= temp;
        float nm = fmaxf(m, s);
        float f = __expf(m - nm), w = __expf(s - nm);
        sw = sw*f + w;
        #pragma unroll
        for (int d2=0;d2<32;d2++) acc[d2] = acc[d2]*f + w*vp[d2][kkx];
        m = nm;
    }
    float inv = 1.f/sw;
    size_t ob = (size_t)b*Np*C_;
    #pragma unroll
    for (int d2=0;d2<32;d2++)
        g_xsa[ob + (size_t)d2*(NHh*Np) + (size_t)h*Np + n] = acc[d2]*inv;  // scrambled flat
}

// ---------------- 7. combine: attn = xs + gamma*(x_ca + x_sa), write (B,C,N) ----------------
__global__ void __launch_bounds__(256) k_combine(const float* __restrict__ gamma)
{
    int b = blockIdx.z, h = blockIdx.y, n0 = blockIdx.x*64;
    __shared__ float A [32][33];
    __shared__ float V [64][33];
    __shared__ float X [64][33];
    __shared__ float Sa[64][33];
    int t = threadIdx.x;
    for (int i=t;i<32*32;i+=256)
        A[i>>5][i&31] = g_attnca[(size_t)(b*NHh+h)*1024 + i];
    for (int i=t;i<64*32;i+=256){
        int nn=i>>5, cc=i&31;
        size_t rq = ((size_t)b*Np + n0+nn)*C4_ + 512 + h*32 + cc;   // v_ca
        size_t rc = ((size_t)b*Np + n0+nn)*C_  + h*32 + cc;
        V [nn][cc] = g_qkvv[rq];
        X [nn][cc] = g_xs [rc];
        Sa[nn][cc] = g_xsa[rc];
    }
    __syncthreads();
    int nl = t & 63, d0 = (t>>6)*8;
    #pragma unroll
    for (int di=0;di<8;di++){
        int dd = d0+di, c = h*32+dd;
        float s = 0.f;
        #pragma unroll
        for (int e=0;e<32;e++) s += A[dd][e]*V[nl][e];
        float val = X[nl][dd] + gamma[c]*(s + Sa[nl][dd]);
        g_skip[((size_t)b*C_ + c)*Np + n0 + nl] = val;
    }
}

// ---------------- 8. 3x3 conv as implicit GEMM (MODE1 fuses bn1+lrelu on input) ----------------
template<int MODE>
__global__ void __launch_bounds__(256) k_conv3(const float* __restrict__ Wc,
                                               const float* __restrict__ bias)
{
    const float* src = MODE ? g_y1 : g_skip;
    float*       dst = MODE ? g_y3 : g_y1;
    __shared__ float As[8][128];
    __shared__ float Bs[8][128];
    int t  = threadIdx.x;
    int n0 = blockIdx.x*128, m0 = blockIdx.y*128;
    int bb = n0>>12, p0 = n0 & 4095;
    int lr = t>>1, lk = (t&1)*4;
    int tm = t>>4, tn = t&15;
    float acc[8][8];
    #pragma unroll
    for (int i=0;i<8;i++)
        #pragma unroll
        for (int j=0;j<8;j++) acc[i][j]=0.f;
    const float* Arow = Wc + (size_t)(m0+lr)*2304 + lk;
    const float* sb   = src + (size_t)bb*C_*Np;
    for (int k0=0;k0<2304;k0+=8){
        float4 av = *(const float4*)(Arow + k0);
        As[lk+0][lr]=av.x; As[lk+1][lr]=av.y; As[lk+2][lr]=av.z; As[lk+3][lr]=av.w;
        #pragma unroll
        for (int i2=0;i2<4;i2++){
            int idx = t + 256*i2;
            int kk = idx>>7, nn = idx&127;
            int k  = k0+kk;
            int ci = k/9; int r = k - ci*9; int ky = r/3; int kx = r - ky*3;
            int p  = p0 + nn;
            int y  = p>>6, x = p&63;
            int iy = y+ky-1, ix = x+kx-1;
            float v = 0.f;
            if ((unsigned)iy < 64u && (unsigned)ix < 64u){
                v = sb[(size_t)ci*Np + iy*64 + ix];
                if (MODE){ v = v*g_s1[ci] + g_sh1[ci]; v = v>=0.f ? v : 0.01f*v; }
            }
            Bs[kk][nn]=v;
        }
        __syncthreads();
        #pragma unroll
        for (int kk=0;kk<8;kk++){
            float4 a0=*(const float4*)&As[kk][tm*8];
            float4 a1=*(const float4*)&As[kk][tm*8+4];
            float4 b0=*(const float4*)&Bs[kk][tn*8];
            float4 b1=*(const float4*)&Bs[kk][tn*8+4];
            float aa[8]={a0.x,a0.y,a0.z,a0.w,a1.x,a1.y,a1.z,a1.w};
            float bbv[8]={b0.x,b0.y,b0.z,b0.w,b1.x,b1.y,b1.z,b1.w};
            #pragma unroll
            for (int i=0;i<8;i++)
                #pragma unroll
                for (int j=0;j<8;j++) acc[i][j] += aa[i]*bbv[j];
        }
        __syncthreads();
    }
    #pragma unroll
    for (int i=0;i<8;i++){
        int co = m0+tm*8+i;
        float bi = bias[co];
        float* drow = dst + ((size_t)bb*C_ + co)*Np + p0 + tn*8;
        #pragma unroll
        for (int j=0;j<8;j++) drow[j] = acc[i][j] + bi;
    }
}

// ---------------- 9. per-channel BN stats (training mode) ----------------
template<int WHICH>
__global__ void k_bnstats(const float* __restrict__ bw, const float* __restrict__ bbeta)
{
    const float* ybuf = WHICH ? g_y3 : g_y1;
    int c = blockIdx.x, t = threadIdx.x;
    float s1=0.f, s2=0.f;
    for (int b2=0;b2<B_;b2++){
        const float* row = ybuf + ((size_t)b2*C_ + c)*Np;
        for (int n=t;n<Np;n+=256){ float v=row[n]; s1+=v; s2+=v*v; }
    }
    __shared__ float r1[256], r2[256];
    r1[t]=s1; r2[t]=s2; __syncthreads();
    for (int o=128;o;o>>=1){ if (t<o){ r1[t]+=r1[t+o]; r2[t]+=r2[t+o]; } __syncthreads(); }
    if (t==0){
        float mean = r1[0]*(1.f/65536.f);
        float var  = r2[0]*(1.f/65536.f) - mean*mean;
        float sc   = bw[c]*rsqrtf(var + 1e-5f);
        if (WHICH){ g_s2[c]=sc; g_sh2[c]=bbeta[c]-mean*sc; }
        else      { g_s1[c]=sc; g_sh1[c]=bbeta[c]-mean*sc; }
    }
}

// ---------------- 10. conv8 1x1 GEMM, fusing bn2 + skip-add + lrelu on input, residuals in epilogue ----------------
__global__ void __launch_bounds__(256) k_final(const float* __restrict__ W8,
                                               const float* __restrict__ b8,
                                               float* __restrict__ out)
{
    __shared__ float As[8][128];
    __shared__ float Bs[8][128];
    int t  = threadIdx.x;
    int n0 = blockIdx.x*128, m0 = blockIdx.y*128;
    int bb = n0>>12, p0 = n0 & 4095;
    int lr = t>>1, lk = (t&1)*4;
    int tm = t>>4, tn = t&15;
    float acc[8][8];
    #pragma unroll
    for (int i=0;i<8;i++)
        #pragma unroll
        for (int j=0;j<8;j++) acc[i][j]=0.f;
    const float* Arow = W8 + (size_t)(m0+lr)*C_ + lk;
    size_t ibase = (size_t)bb*C_*Np + p0;
    for (int k0=0;k0<C_;k0+=8){
        float4 av = *(const float4*)(Arow + k0);
        As[lk+0][lr]=av.x; As[lk+1][lr]=av.y; As[lk+2][lr]=av.z; As[lk+3][lr]=av.w;
        #pragma unroll
        for (int i2=0;i2<4;i2++){
            int idx = t + 256*i2;
            int kk = idx>>7, nn = idx&127;
            int ci = k0+kk;
            size_t a = ibase + (size_t)ci*Np + nn;
            float v = g_y3[a]*g_s2[ci] + g_sh2[ci] + g_skip[a];   // bn2 + skip
            Bs[kk][nn] = v>=0.f ? v : 0.01f*v;                    // lrelu
        }
        __syncthreads();
        #pragma unroll
        for (int kk=0;kk<8;kk++){
            float4 a0=*(const float4*)&As[kk][tm*8];
            float4 a1=*(const float4*)&As[kk][tm*8+4];
            float4 b0=*(const float4*)&Bs[kk][tn*8];
            float4 b1=*(const float4*)&Bs[kk][tn*8+4];
            float aa[8]={a0.x,a0.y,a0.z,a0.w,a1.x,a1.y,a1.z,a1.w};
            float bbv[8]={b0.x,b0.y,b0.z,b0.w,b1.x,b1.y,b1.z,b1.w};
            #pragma unroll
            for (int i=0;i<8;i++)
                #pragma unroll
                for (int j=0;j<8;j++) acc[i][j] += aa[i]*bbv[j];
        }
        __syncthreads();
    }
    #pragma unroll
    for (int i=0;i<8;i++){
        int co = m0+tm*8+i;
        float bi = b8[co];
        size_t obase = ((size_t)bb*C_ + co)*Np + p0 + tn*8;
        #pragma unroll
        for (int j=0;j<8;j++)
            out[obase+j] = acc[i][j] + g_skip[obase+j] + bi;
    }
}

// ---------------- launch ----------------
extern "C" void kernel_launch(void* const* d_in, const int* in_sizes, int n_in,
                              void* d_out, int out_size)
{
    const float* x       = (const float*)d_in[0];
    const float* w_qkvv  = (const float*)d_in[1];
    const float* ef      = (const float*)d_in[2];
    const float* t2      = (const float*)d_in[3];
    const float* ln_w    = (const float*)d_in[4];
    const float* ln_b    = (const float*)d_in[5];
    const float* gamma   = (const float*)d_in[6];
    const float* conv1_w = (const float*)d_in[7];
    const float* conv1_b = (const float*)d_in[8];
    const float* bn1_w   = (const float*)d_in[9];
    const float* bn1_b   = (const float*)d_in[10];
    const float* conv2_w = (const float*)d_in[11];
    const float* conv2_b = (const float*)d_in[12];
    const float* bn2_w   = (const float*)d_in[13];
    const float* bn2_b   = (const float*)d_in[14];
    const float* conv8_w = (const float*)d_in[15];
    const float* conv8_b = (const float*)d_in[16];
    float* out = (float*)d_out;

    k_tln       <<<dim3(Np/32, B_), 256>>>(x, ln_w, ln_b);
    k_gemm_qkvv <<<dim3(C4_/128, (B_*Np)/128), 256>>>(w_qkvv);
    k_zerosumsq <<<8, 1024>>>();
    k_colsumsq  <<<dim3(16, B_), 512>>>();
    k_kvproj    <<<dim3(4, 2, B_), 256>>>(ef);
    k_gram      <<<dim3(NHh, B_), 1024>>>();
    k_spatial   <<<dim3(Np/128, NHh, B_), 128>>>(t2);
    k_combine   <<<dim3(Np/64, NHh, B_), 256>>>(gamma);
    k_conv3<0>  <<<dim3((B_*Np)/128, 2), 256>>>(conv1_w, conv1_b);
    k_bnstats<0><<<C_, 256>>>(bn1_w, bn1_b);
    k_conv3<1>  <<<dim3((B_*Np)/128, 2), 256>>>(conv2_w, conv2_b);
    k_bnstats<1><<<C_, 256>>>(bn2_w, bn2_b);
    k_final     <<<dim3((B_*Np)/128, 2), 256>>>(conv8_w, conv8_b, out);
}

// round 7
// speedup vs baseline: 2.1456x; 2.1456x over previous
#include <cuda_runtime.h>
#include <cstdint>

#define B_   16
#define C_   256
#define NHh  8
#define Dh   32
#define Np   4096
#define Kl   64
#define C4_  1024

// ---------------- scratch (static __device__; no allocation) ----------------
// Aliasing by lifetime to stay under the device-memory budget:
//   g_hswz (dead after qkvv mma)  ALIASES g_y1 (first written by conv1 mma)
//   g_h    (dead after k_swz)     ALIASES g_y3 (first written by conv2 mma)
__device__ float g_xs  [(size_t)B_*Np*C_];    // (B,N,C) input transposed
__device__ float g_qkvv[(size_t)B_*Np*C4_];   // GEMM1 output (B,N,1024)
__device__ float g_wt  [(size_t)C_*C4_];      // w_qkvv transposed [256][1024], tf32
__device__ float g_w1s [(size_t)C_*2304];     // conv1 weights swizzled (tf32)
__device__ float g_w2s [(size_t)C_*2304];
__device__ float g_w8s [(size_t)C_*C_];
__device__ float g_sumsq[B_*512];             // col sum-of-squares (q 0..255, k 256..511)
__device__ float g_kproj[B_*C_*Kl];
__device__ float g_vproj[B_*C_*Kl];
__device__ float g_attnca[B_*NHh*Dh*Dh];
__device__ float g_xsa [(size_t)B_*Np*C_];
__device__ float g_skip[(size_t)B_*C_*Np];    // attn_skip (B,C,N)
__device__ float g_y1  [(size_t)B_*C_*Np];    // conv1 raw  / earlier: swizzled LN tokens
__device__ float g_y3  [(size_t)B_*C_*Np];    // conv2 raw  / earlier: LN output row-major
__device__ float g_s1[C_], g_sh1[C_], g_s2[C_], g_sh2[C_];

#define g_hswz g_y1
#define g_h    g_y3

__device__ __forceinline__ float tf32r(float x){
    uint32_t u; asm("cvt.rna.tf32.f32 %0, %1;" : "=r"(u) : "f"(x));
    return __uint_as_float(u);
}

// ---------------- 1. transpose + LayerNorm ----------------
__global__ void k_tln(const float* __restrict__ x, const float* __restrict__ lw,
                      const float* __restrict__ lb)
{
    __shared__ float sm[32][C_+1];
    int b = blockIdx.y, n0 = blockIdx.x*32;
    int tx = threadIdx.x & 31, ty = threadIdx.x >> 5;     // 8 warps
    const float* xb = x + (size_t)b*C_*Np + n0 + tx;
    #pragma unroll
    for (int c = ty; c < C_; c += 8)
        sm[tx][c] = xb[(size_t)c*Np];
    __syncthreads();
    #pragma unroll
    for (int rr = 0; rr < 4; ++rr){
        int r = ty*4 + rr;
        float s1 = 0.f, s2 = 0.f;
        #pragma unroll
        for (int c = tx; c < C_; c += 32){ float v = sm[r][c]; s1 += v; s2 += v*v; }
        #pragma unroll
        for (int o = 16; o; o >>= 1){
            s1 += __shfl_xor_sync(0xffffffffu, s1, o);
            s2 += __shfl_xor_sync(0xffffffffu, s2, o);
        }
        float mean = s1 * (1.f/C_);
        float var  = s2 * (1.f/C_) - mean*mean;
        float rstd = rsqrtf(var + 1e-5f);
        size_t row = ((size_t)b*Np + n0 + r)*C_;
        #pragma unroll
        for (int c = tx; c < C_; c += 32){
            float v = sm[r][c];
            g_xs[row+c] = v;
            g_h [row+c] = (v-mean)*rstd*lw[c] + lb[c];
        }
    }
}

// ---------------- A-swizzle: row-major MxK -> mma fragment layout, tf32 ----------------
__global__ void k_swz(const float* __restrict__ src, float* __restrict__ dst, int Ktiles)
{
    int u = blockIdx.x*256 + threadIdx.x;
    int lane = u & 31, kstep = (u>>5)&1, mtile = (u>>6)&7;
    int rest = u>>9;
    int ktile = rest % Ktiles, m_blk = rest / Ktiles;
    int K = Ktiles*16;
    float v[4];
    #pragma unroll
    for (int i=0;i<4;i++){
        int m = m_blk*128 + mtile*16 + (lane>>2) + (i&1)*8;
        int k = ktile*16 + kstep*8 + (lane&3) + ((i>>1)&1)*4;
        v[i] = tf32r(src[(size_t)m*K + k]);
    }
    *(float4*)&dst[(size_t)u*4] = make_float4(v[0],v[1],v[2],v[3]);
}

// ---------------- transpose w_qkvv [1024][256] -> g_wt [256][1024], tf32 ----------------
__global__ void k_wt_tr(const float* __restrict__ w)
{
    __shared__ float sm[32][33];
    int bx = blockIdx.x, by = blockIdx.y;
    int tx = threadIdx.x & 31, ty = threadIdx.x >> 5;
    for (int r=ty;r<32;r+=8) sm[r][tx] = w[(size_t)(by*32+r)*C_ + bx*32+tx];
    __syncthreads();
    for (int r=ty;r<32;r+=8)
        g_wt[(size_t)(bx*32+r)*C4_ + by*32+tx] = tf32r(sm[tx][r]);
}

// ---------------- tf32 MMA GEMM ----------------
// block 128x128, 256 thr (8 warps, 2x4), warp tile 64x32, k-tile 16, double-buffered.
// MODE 0: qkvv  (A = swizzled tokens,  B = g_wt,        out = g_qkvv token-major)
// MODE 1: conv1 (A = g_w1s, B = im2col(g_skip),         out = g_y1 + bias)
// MODE 2: conv2 (A = g_w2s, B = im2col(bn1+lrelu(g_y1)),out = g_y3 + bias)
// MODE 3: conv8 (A = g_w8s, B = lrelu(bn2(g_y3)+skip),  out = final + bias + skip)
template<int MODE, int KDIM>
__global__ void __launch_bounds__(256) k_mma(const float* __restrict__ Aswz,
                                             const float* __restrict__ bias,
                                             float* __restrict__ dst)
{
    constexpr int KT = KDIM/16;
    __shared__ float sA[2][2048];
    __shared__ float sB[2][16*136];
    int t = threadIdx.x;
    int n0 = blockIdx.x*128, m0 = blockIdx.y*128;
    int bb = n0>>12, p0 = n0&4095;
    int w = t>>5, lane = t&31;
    int wm = w>>2, wn = w&3;

    float acc[4][4][4];
    #pragma unroll
    for (int a=0;a<4;a++)
        #pragma unroll
        for (int b2=0;b2<4;b2++)
            #pragma unroll
            for (int c=0;c<4;c++) acc[a][b2][c]=0.f;

    const float* Ablk = Aswz + (size_t)blockIdx.y*KT*2048;
    int nn = t & 127;
    int yy = (p0+nn)>>6, xx = (p0+nn)&63;       // conv pixel coords (MODE 1/2)
    int kk0 = t>>7;                             // thread's base kk (0 or 1)

    float4 pa0, pa1;
    float  pv[8];

    auto loadA = [&](int kt){
        const float4* p = (const float4*)(Ablk + (size_t)kt*2048) + t*2;
        pa0 = p[0]; pa1 = p[1];
    };
    auto genB = [&](int it){
        int k0 = it*16;
        if (MODE == 0){
            #pragma unroll
            for (int i2=0;i2<8;i2++)
                pv[i2] = g_wt[(size_t)(k0 + kk0 + 2*i2)*C4_ + n0 + nn];
        } else if (MODE == 3){
            #pragma unroll
            for (int i2=0;i2<8;i2++){
                int ci = k0 + kk0 + 2*i2;
                size_t a = ((size_t)bb*C_ + ci)*Np + p0 + nn;
                float v = g_y3[a]*g_s2[ci] + g_sh2[ci] + g_skip[a];
                pv[i2] = tf32r(v >= 0.f ? v : 0.01f*v);
            }
        } else {
            const float* src = (MODE==1) ? g_skip : g_y1;
            const float* sb2 = src + (size_t)bb*C_*Np;
            int kg = k0 + kk0;
            int ci = kg/9; int r = kg - ci*9;
            #pragma unroll
            for (int i2=0;i2<8;i2++){
                int ky = r/3, kx = r - ky*3;
                int iy = yy + ky - 1, ix = xx + kx - 1;
                float v = 0.f;
                if ((unsigned)iy < 64u && (unsigned)ix < 64u){
                    v = sb2[(size_t)ci*Np + iy*64 + ix];
                    if (MODE==2){ v = v*g_s1[ci] + g_sh1[ci]; v = v>=0.f ? v : 0.01f*v; }
                }
                pv[i2] = tf32r(v);
                r += 2; if (r >= 9){ r -= 9; ci++; }
            }
        }
    };
    auto stage = [&](int buf){
        *(float4*)&sA[buf][t*8]   = pa0;
        *(float4*)&sA[buf][t*8+4] = pa1;
        #pragma unroll
        for (int i2=0;i2<8;i2++)
            sB[buf][(kk0 + 2*i2)*136 + nn] = pv[i2];
    };
    auto compute = [&](int buf){
        #pragma unroll
        for (int ks=0; ks<2; ++ks){
            uint4 a[4];
            #pragma unroll
            for (int mt=0;mt<4;mt++)
                a[mt] = *(const uint4*)&sA[buf][(((wm*4+mt)*2 + ks)*32 + lane)*4];
            uint32_t b0[4], b1[4];
            #pragma unroll
            for (int nt=0;nt<4;nt++){
                int n = (wn*4+nt)*8 + (lane>>2);
                b0[nt] = __float_as_uint(sB[buf][(ks*8 +     (lane&3))*136 + n]);
                b1[nt] = __float_as_uint(sB[buf][(ks*8 + 4 + (lane&3))*136 + n]);
            }
            #pragma unroll
            for (int mt=0;mt<4;mt++)
                #pragma unroll
                for (int nt=0;nt<4;nt++){
                    float* c = acc[mt][nt];
                    asm volatile(
                      "mma.sync.aligned.m16n8k8.row.col.f32.tf32.tf32.f32 "
                      "{%0,%1,%2,%3},{%4,%5,%6,%7},{%8,%9},{%0,%1,%2,%3};"
                      : "+f"(c[0]),"+f"(c[1]),"+f"(c[2]),"+f"(c[3])
                      : "r"(a[mt].x),"r"(a[mt].y),"r"(a[mt].z),"r"(a[mt].w),
                        "r"(b0[nt]),"r"(b1[nt]));
                }
        }
    };

    loadA(0); genB(0);
    stage(0);
    __syncthreads();
    for (int it=0; it<KT; ++it){
        int buf = it & 1;
        if (it+1 < KT){ loadA(it+1); genB(it+1); }
        compute(buf);
        if (it+1 < KT) stage(buf^1);
        __syncthreads();
    }

    // ---------------- epilogue ----------------
    if (MODE == 0){
        #pragma unroll
        for (int mt=0;mt<4;mt++){
            int row = m0 + (wm*4+mt)*16 + (lane>>2);
            #pragma unroll
            for (int nt=0;nt<4;nt++){
                int col = n0 + (wn*4+nt)*8 + (lane&3)*2;
                float* d0 = dst + (size_t)row*C4_ + col;
                *(float2*)d0            = make_float2(acc[mt][nt][0], acc[mt][nt][1]);
                *(float2*)(d0 + 8*C4_)  = make_float2(acc[mt][nt][2], acc[mt][nt][3]);
            }
        }
    } else {
        #pragma unroll
        for (int mt=0;mt<4;mt++){
            int co = m0 + (wm*4+mt)*16 + (lane>>2);
            float bi0 = bias[co], bi1 = bias[co+8];
            #pragma unroll
            for (int nt=0;nt<4;nt++){
                int p = p0 + (wn*4+nt)*8 + (lane&3)*2;
                size_t o0 = ((size_t)bb*C_ + co)*Np + p;
                size_t o1 = o0 + 8*(size_t)Np;
                if (MODE == 3){
                    *(float2*)(dst+o0) = make_float2(acc[mt][nt][0]+bi0+g_skip[o0],
                                                     acc[mt][nt][1]+bi0+g_skip[o0+1]);
                    *(float2*)(dst+o1) = make_float2(acc[mt][nt][2]+bi1+g_skip[o1],
                                                     acc[mt][nt][3]+bi1+g_skip[o1+1]);
                } else {
                    *(float2*)(dst+o0) = make_float2(acc[mt][nt][0]+bi0, acc[mt][nt][1]+bi0);
                    *(float2*)(dst+o1) = make_float2(acc[mt][nt][2]+bi1, acc[mt][nt][3]+bi1);
                }
            }
        }
    }
}

// ---------------- q/k column sum-of-squares ----------------
__global__ void k_zerosumsq(){
    int i = blockIdx.x*1024 + threadIdx.x;
    if (i < B_*512) g_sumsq[i] = 0.f;
}
__global__ void k_colsumsq(){
    int b = blockIdx.y, chunk = blockIdx.x;
    int c = threadIdx.x;
    size_t base = (size_t)b*Np*C4_ + (size_t)chunk*256*C4_;
    float s = 0.f;
    for (int n=0;n<256;n++){ float v = g_qkvv[base + (size_t)n*C4_ + c]; s += v*v; }
    atomicAdd(&g_sumsq[b*512 + c], s);
}

// ---------------- k_proj / v_proj ----------------
__global__ void __launch_bounds__(256) k_kvproj(const float* __restrict__ ef)
{
    int b = blockIdx.z, which = blockIdx.y, c0 = blockIdx.x*64;
    int basecol = which ? 768 : 256;
    float* outp = which ? g_vproj : g_kproj;
    __shared__ float a_s[32][65];
    __shared__ float e_s[32][65];
    int t = threadIdx.x, tm = t>>4, tn = t&15;
    float acc[4][4];
    #pragma unroll
    for (int i=0;i<4;i++)
        #pragma unroll
        for (int j=0;j<4;j++) acc[i][j]=0.f;
    for (int n0=0;n0<Np;n0+=32){
        for (int i=t;i<32*64;i+=256){
            int nn=i>>6, cc=i&63;
            a_s[nn][cc] = g_qkvv[((size_t)b*Np + n0+nn)*C4_ + basecol + c0 + cc];
        }
        for (int i=t;i<32*64;i+=256){
            int nn=i>>6, cc=i&63;
            e_s[nn][cc] = ef[(size_t)(n0+nn)*Kl + cc];
        }
        __syncthreads();
        #pragma unroll 8
        for (int nn=0;nn<32;nn++){
            float ra[4], rb[4];
            #pragma unroll
            for (int i=0;i<4;i++) ra[i]=a_s[nn][tm*4+i];
            #pragma unroll
            for (int j=0;j<4;j++) rb[j]=e_s[nn][tn*4+j];
            #pragma unroll
            for (int i=0;i<4;i++)
                #pragma unroll
                for (int j=0;j<4;j++) acc[i][j] += ra[i]*rb[j];
        }
        __syncthreads();
    }
    #pragma unroll
    for (int i=0;i<4;i++)
        #pragma unroll
        for (int j=0;j<4;j++)
            outp[(size_t)b*C_*Kl + (size_t)(c0+tm*4+i)*Kl + tn*4+j] = acc[i][j];
}

// ---------------- channel-attn gram + softmax ----------------
__global__ void __launch_bounds__(1024) k_gram()
{
    int h = blockIdx.x, b = blockIdx.y;
    int t = threadIdx.x, dd = t>>5, e = t&31;
    __shared__ float sm[64][65];
    float s = 0.f;
    for (int n0=0;n0<Np;n0+=64){
        for (int i=t;i<64*64;i+=1024){
            int nnq=i>>6, cc=i&63;
            int col = (cc<32) ? (h*32+cc) : (256 + h*32 + (cc-32));
            sm[nnq][cc] = g_qkvv[((size_t)b*Np + n0+nnq)*C4_ + col];
        }
        __syncthreads();
        #pragma unroll 16
        for (int nnq=0;nnq<64;nnq++) s += sm[nnq][dd]*sm[nnq][32+e];
        __syncthreads();
    }
    float nq = sqrtf(g_sumsq[b*512 +       h*32 + dd]);
    float nk = sqrtf(g_sumsq[b*512 + 256 + h*32 + e ]);
    float logit = s / fmaxf(nq,1e-12f) / fmaxf(nk,1e-12f) * (1.0f/64.0f);
    float mx = logit;
    #pragma unroll
    for (int o=16;o;o>>=1) mx = fmaxf(mx, __shfl_xor_sync(0xffffffffu, mx, o));
    float ew = __expf(logit - mx);
    float sw = ew;
    #pragma unroll
    for (int o=16;o;o>>=1) sw += __shfl_xor_sync(0xffffffffu, sw, o);
    g_attnca[((size_t)(b*NHh+h)*Dh + dd)*Dh + e] = ew/sw;
}

// ---------------- spatial attention ----------------
__global__ void __launch_bounds__(128) k_spatial(const float* __restrict__ t2)
{
    int b = blockIdx.z, h = blockIdx.y;
    int n = blockIdx.x*128 + threadIdx.x;
    __shared__ float kp[32][65];
    __shared__ float vp[32][65];
    __shared__ float iq_s[32];
    int t = threadIdx.x;
    for (int i=t;i<32*64;i+=128){
        int ddi=i>>6, kki=i&63;
        size_t o = (size_t)b*C_*Kl + (size_t)(h*32+ddi)*Kl + kki;
        kp[ddi][kki]=g_kproj[o];
        vp[ddi][kki]=g_vproj[o];
    }
    if (t<32) iq_s[t] = 1.f/fmaxf(sqrtf(g_sumsq[b*512 + h*32 + t]), 1e-12f);
    __syncthreads();
    float q[32];
    size_t qb = ((size_t)b*Np + n)*C4_ + h*32;
    const float4* qv = (const float4*)(g_qkvv + qb);
    #pragma unroll
    for (int i=0;i<8;i++){
        float4 v = qv[i];
        q[4*i+0]=v.x*iq_s[4*i+0]; q[4*i+1]=v.y*iq_s[4*i+1];
        q[4*i+2]=v.z*iq_s[4*i+2]; q[4*i+3]=v.w*iq_s[4*i+3];
    }
    float temp = t2[h];
    float m = -1e30f, sw = 0.f, acc[32];
    #pragma unroll
    for (int d2=0;d2<32;d2++) acc[d2]=0.f;
    for (int kkx=0;kkx<64;kkx++){
        float s = 0.f;
        #pragma unroll
        for (int d2=0;d2<32;d2++) s += q[d2]*kp[d2][kkx];
        s *= temp;
        float nm = fmaxf(m, s);
        float f = __expf(m - nm), w2 = __expf(s - nm);
        sw = sw*f + w2;
        #pragma unroll
        for (int d2=0;d2<32;d2++) acc[d2] = acc[d2]*f + w2*vp[d2][kkx];
        m = nm;
    }
    float inv = 1.f/sw;
    size_t ob = (size_t)b*Np*C_;
    #pragma unroll
    for (int d2=0;d2<32;d2++)
        g_xsa[ob + (size_t)d2*(NHh*Np) + (size_t)h*Np + n] = acc[d2]*inv;
}

// ---------------- combine ----------------
__global__ void __launch_bounds__(256) k_combine(const float* __restrict__ gamma)
{
    int b = blockIdx.z, h = blockIdx.y, n0 = blockIdx.x*64;
    __shared__ float A [32][33];
    __shared__ float V [64][33];
    __shared__ float X [64][33];
    __shared__ float Sa[64][33];
    int t = threadIdx.x;
    for (int i=t;i<32*32;i+=256)
        A[i>>5][i&31] = g_attnca[(size_t)(b*NHh+h)*1024 + i];
    for (int i=t;i<64*32;i+=256){
        int nnx=i>>5, cc=i&31;
        size_t rq = ((size_t)b*Np + n0+nnx)*C4_ + 512 + h*32 + cc;
        size_t rc = ((size_t)b*Np + n0+nnx)*C_  + h*32 + cc;
        V [nnx][cc] = g_qkvv[rq];
        X [nnx][cc] = g_xs [rc];
        Sa[nnx][cc] = g_xsa[rc];
    }
    __syncthreads();
    int nl = t & 63, d0 = (t>>6)*8;
    #pragma unroll
    for (int di=0;di<8;di++){
        int dd = d0+di, c = h*32+dd;
        float s = 0.f;
        #pragma unroll
        for (int e=0;e<32;e++) s += A[dd][e]*V[nl][e];
        float val = X[nl][dd] + gamma[c]*(s + Sa[nl][dd]);
        g_skip[((size_t)b*C_ + c)*Np + n0 + nl] = val;
    }
}

// ---------------- BN stats ----------------
template<int WHICH>
__global__ void k_bnstats(const float* __restrict__ bw, const float* __restrict__ bbeta)
{
    const float* ybuf = WHICH ? g_y3 : g_y1;
    int c = blockIdx.x, t = threadIdx.x;
    float s1=0.f, s2=0.f;
    for (int b2=0;b2<B_;b2++){
        const float* row = ybuf + ((size_t)b2*C_ + c)*Np;
        for (int n=t;n<Np;n+=256){ float v=row[n]; s1+=v; s2+=v*v; }
    }
    __shared__ float r1[256], r2[256];
    r1[t]=s1; r2[t]=s2; __syncthreads();
    for (int o=128;o;o>>=1){ if (t<o){ r1[t]+=r1[t+o]; r2[t]+=r2[t+o]; } __syncthreads(); }
    if (t==0){
        float mean = r1[0]*(1.f/65536.f);
        float var  = r2[0]*(1.f/65536.f) - mean*mean;
        float sc   = bw[c]*rsqrtf(var + 1e-5f);
        if (WHICH){ g_s2[c]=sc; g_sh2[c]=bbeta[c]-mean*sc; }
        else      { g_s1[c]=sc; g_sh1[c]=bbeta[c]-mean*sc; }
    }
}

// ---------------- launch ----------------
extern "C" void kernel_launch(void* const* d_in, const int* in_sizes, int n_in,
                              void* d_out, int out_size)
{
    const float* x       = (const float*)d_in[0];
    const float* w_qkvv  = (const float*)d_in[1];
    const float* ef      = (const float*)d_in[2];
    const float* t2      = (const float*)d_in[3];
    const float* ln_w    = (const float*)d_in[4];
    const float* ln_b    = (const float*)d_in[5];
    const float* gamma   = (const float*)d_in[6];
    const float* conv1_w = (const float*)d_in[7];
    const float* conv1_b = (const float*)d_in[8];
    const float* bn1_w   = (const float*)d_in[9];
    const float* bn1_b   = (const float*)d_in[10];
    const float* conv2_w = (const float*)d_in[11];
    const float* conv2_b = (const float*)d_in[12];
    const float* bn2_w   = (const float*)d_in[13];
    const float* bn2_b   = (const float*)d_in[14];
    const float* conv8_w = (const float*)d_in[15];
    const float* conv8_b = (const float*)d_in[16];
    float* out = (float*)d_out;

    float *p_hswz, *p_w1s, *p_w2s, *p_w8s, *p_qkvv, *p_h;
    cudaGetSymbolAddress((void**)&p_hswz, g_y1);   // alias: swizzled LN tokens
    cudaGetSymbolAddress((void**)&p_h,    g_y3);   // alias: LN output row-major
    cudaGetSymbolAddress((void**)&p_w1s, g_w1s);
    cudaGetSymbolAddress((void**)&p_w2s, g_w2s);
    cudaGetSymbolAddress((void**)&p_w8s, g_w8s);
    cudaGetSymbolAddress((void**)&p_qkvv, g_qkvv);
    float *p_y1, *p_y3;
    cudaGetSymbolAddress((void**)&p_y1, g_y1);
    cudaGetSymbolAddress((void**)&p_y3, g_y3);

    // weight prep (independent of activations)
    k_wt_tr <<<dim3(8,32), 256>>>(w_qkvv);
    k_swz   <<<2*144*2, 256>>>(conv1_w, p_w1s, 144);
    k_swz   <<<2*144*2, 256>>>(conv2_w, p_w2s, 144);
    k_swz   <<<2*16*2,  256>>>(conv8_w, p_w8s, 16);

    k_tln   <<<dim3(Np/32, B_), 256>>>(x, ln_w, ln_b);
    k_swz   <<<512*16*2, 256>>>(p_h, p_hswz, 16);
    k_mma<0,256> <<<dim3(8, 512), 256>>>(p_hswz, ln_b /*unused*/, p_qkvv);

    k_zerosumsq <<<8, 1024>>>();
    k_colsumsq  <<<dim3(16, B_), 512>>>();
    k_kvproj    <<<dim3(4, 2, B_), 256>>>(ef);
    k_gram      <<<dim3(NHh, B_), 1024>>>();
    k_spatial   <<<dim3(Np/128, NHh, B_), 128>>>(t2);
    k_combine   <<<dim3(Np/64, NHh, B_), 256>>>(gamma);

    k_mma<1,2304> <<<dim3(512, 2), 256>>>(p_w1s, conv1_b, p_y1);
    k_bnstats<0>  <<<C_, 256>>>(bn1_w, bn1_b);
    k_mma<2,2304> <<<dim3(512, 2), 256>>>(p_w2s, conv2_b, p_y3);
    k_bnstats<1>  <<<C_, 256>>>(bn2_w, bn2_b);
    k_mma<3,256>  <<<dim3(512, 2), 256>>>(p_w8s, conv8_b, out);
}